// round 2
// baseline (speedup 1.0000x reference)
#include <cuda_runtime.h>

#define N_NODES 50000
#define E_EDGES 600000
#define IN_DIM  256
#define OUT_DIM 128
#define SCALE   1.8f
#define ALPHA   0.15f
#define ONE_MA  0.85f
#define EPS_N   1e-12f

// Scratch (device globals: allocation-free)
__device__ float g_h  [(size_t)N_NODES * OUT_DIM];
__device__ float g_z  [(size_t)N_NODES * OUT_DIM];
__device__ float g_agg[(size_t)N_NODES * OUT_DIM];
__device__ float g_deg [N_NODES];
__device__ float g_dinv[N_NODES];

// ---------------------------------------------------------------------------
// init: zero agg, deg = 1 (self loop)
__global__ void k_init() {
    int idx = blockIdx.x * blockDim.x + threadIdx.x;
    if (idx < N_NODES * OUT_DIM) g_agg[idx] = 0.0f;
    if (idx < N_NODES) g_deg[idx] = 1.0f;
}

// degree histogram over targets (col)  -- edge_index is int32 (JAX x64 off)
__global__ void k_deg(const int* __restrict__ ei) {
    int e = blockIdx.x * blockDim.x + threadIdx.x;
    if (e < E_EDGES) {
        int c = ei[E_EDGES + e];
        atomicAdd(&g_deg[c], 1.0f);
    }
}

__global__ void k_dinv() {
    int i = blockIdx.x * blockDim.x + threadIdx.x;
    if (i < N_NODES) g_dinv[i] = rsqrtf(g_deg[i]);   // deg >= 1 always
}

// ---------------------------------------------------------------------------
// GEMM: h = normalize(x @ W^T + b) * SCALE
// 128x128 tile, BK=8, 256 threads, 8x8 per thread, fused bias + L2 norm.
__global__ void __launch_bounds__(256) k_gemm(const float* __restrict__ X,
                                              const float* __restrict__ W,
                                              const float* __restrict__ B) {
    __shared__ float Xs[8][128];
    __shared__ float Ws[8][128];
    __shared__ float red[128][17];

    int tid = threadIdx.x;
    int tx = tid & 15;        // 0..15 -> col group
    int ty = tid >> 4;        // 0..15 -> row group
    int row0 = blockIdx.x * 128;

    int lr = tid >> 1;        // 0..127 (row/col within tile for loads)
    int lk = (tid & 1) * 4;   // 0 or 4

    float c[8][8];
#pragma unroll
    for (int i = 0; i < 8; i++)
#pragma unroll
        for (int j = 0; j < 8; j++) c[i][j] = 0.0f;

    for (int k0 = 0; k0 < IN_DIM; k0 += 8) {
        float4 xv = make_float4(0.f, 0.f, 0.f, 0.f);
        int grow = row0 + lr;
        if (grow < N_NODES)
            xv = *(const float4*)(X + (size_t)grow * IN_DIM + k0 + lk);
        Xs[lk + 0][lr] = xv.x; Xs[lk + 1][lr] = xv.y;
        Xs[lk + 2][lr] = xv.z; Xs[lk + 3][lr] = xv.w;

        float4 wv = *(const float4*)(W + (size_t)lr * IN_DIM + k0 + lk);
        Ws[lk + 0][lr] = wv.x; Ws[lk + 1][lr] = wv.y;
        Ws[lk + 2][lr] = wv.z; Ws[lk + 3][lr] = wv.w;
        __syncthreads();

#pragma unroll
        for (int k = 0; k < 8; k++) {
            float4 a0 = *(float4*)&Xs[k][ty * 8];
            float4 a1 = *(float4*)&Xs[k][ty * 8 + 4];
            float4 b0 = *(float4*)&Ws[k][tx * 8];
            float4 b1 = *(float4*)&Ws[k][tx * 8 + 4];
            float aa[8] = {a0.x, a0.y, a0.z, a0.w, a1.x, a1.y, a1.z, a1.w};
            float bb[8] = {b0.x, b0.y, b0.z, b0.w, b1.x, b1.y, b1.z, b1.w};
#pragma unroll
            for (int i = 0; i < 8; i++)
#pragma unroll
                for (int j = 0; j < 8; j++) c[i][j] += aa[i] * bb[j];
        }
        __syncthreads();
    }

    // bias
    float bb[8];
#pragma unroll
    for (int j = 0; j < 8; j++) bb[j] = B[tx * 8 + j];
#pragma unroll
    for (int i = 0; i < 8; i++)
#pragma unroll
        for (int j = 0; j < 8; j++) c[i][j] += bb[j];

    // per-row sum of squares
#pragma unroll
    for (int i = 0; i < 8; i++) {
        float p = 0.f;
#pragma unroll
        for (int j = 0; j < 8; j++) p += c[i][j] * c[i][j];
        red[ty * 8 + i][tx] = p;
    }
    __syncthreads();

#pragma unroll
    for (int i = 0; i < 8; i++) {
        int r = ty * 8 + i;
        float tot = 0.f;
#pragma unroll
        for (int t = 0; t < 16; t++) tot += red[r][t];
        float s = SCALE / fmaxf(sqrtf(tot), EPS_N);
        int grow = row0 + r;
        if (grow < N_NODES) {
            float* outp = g_h + (size_t)grow * OUT_DIM + tx * 8;
            float4 o0 = make_float4(c[i][0] * s, c[i][1] * s, c[i][2] * s, c[i][3] * s);
            float4 o1 = make_float4(c[i][4] * s, c[i][5] * s, c[i][6] * s, c[i][7] * s);
            *(float4*)outp       = o0;
            *(float4*)(outp + 4) = o1;
        }
    }
}

// ---------------------------------------------------------------------------
// scatter: for each edge, agg[col] += dinv[row]*dinv[col] * src[row]
// one warp per edge; vectorized red.global.add.v4.f32 (sm_90+)
__global__ void __launch_bounds__(256) k_scatter(const int* __restrict__ ei,
                                                 int src_sel /*0=h,1=z*/) {
    int gwarp = (blockIdx.x * blockDim.x + threadIdx.x) >> 5;
    int lane  = threadIdx.x & 31;
    if (gwarp >= E_EDGES) return;

    int r = ei[gwarp];
    int c = ei[E_EDGES + gwarp];
    float w = g_dinv[r] * g_dinv[c];

    const float* src = src_sel ? g_z : g_h;
    float4 v = *(const float4*)(src + (size_t)r * OUT_DIM + lane * 4);
    float* dst = g_agg + (size_t)c * OUT_DIM + lane * 4;
    asm volatile("red.global.add.v4.f32 [%0], {%1,%2,%3,%4};"
                 :: "l"(dst), "f"(v.x * w), "f"(v.y * w), "f"(v.z * w), "f"(v.w * w)
                 : "memory");
}

// ---------------------------------------------------------------------------
// update: dst = 0.85*(agg + dinv[i]^2 * src) + 0.15*h ; optionally clear agg
__global__ void __launch_bounds__(256) k_update(int src_sel /*0=h,1=z*/,
                                                float* __restrict__ out,
                                                int use_out /*else write g_z*/,
                                                int clear) {
    int idx = blockIdx.x * blockDim.x + threadIdx.x;   // float4 index
    const int total = N_NODES * OUT_DIM / 4;
    if (idx >= total) return;
    int node = idx >> 5;                               // 32 float4 per node
    float d = g_dinv[node];
    float sw = d * d;

    const float4* srcp = src_sel ? (const float4*)g_z : (const float4*)g_h;
    float4 a = ((float4*)g_agg)[idx];
    float4 s = srcp[idx];
    float4 hh = ((const float4*)g_h)[idx];
    float4 o;
    o.x = ONE_MA * (a.x + sw * s.x) + ALPHA * hh.x;
    o.y = ONE_MA * (a.y + sw * s.y) + ALPHA * hh.y;
    o.z = ONE_MA * (a.z + sw * s.z) + ALPHA * hh.z;
    o.w = ONE_MA * (a.w + sw * s.w) + ALPHA * hh.w;

    float4* dstp = use_out ? (float4*)out : (float4*)g_z;
    dstp[idx] = o;
    if (clear) ((float4*)g_agg)[idx] = make_float4(0.f, 0.f, 0.f, 0.f);
}

// ---------------------------------------------------------------------------
extern "C" void kernel_launch(void* const* d_in, const int* in_sizes, int n_in,
                              void* d_out, int out_size) {
    const float* x  = (const float*)d_in[0];
    const int*   ei = (const int*)d_in[1];
    const float* W  = (const float*)d_in[2];
    const float* b  = (const float*)d_in[3];
    float* out = (float*)d_out;

    const int TOT = N_NODES * OUT_DIM;

    k_init<<<(TOT + 255) / 256, 256>>>();
    k_deg <<<(E_EDGES + 255) / 256, 256>>>(ei);
    k_dinv<<<(N_NODES + 255) / 256, 256>>>();
    k_gemm<<<(N_NODES + 127) / 128, 256>>>(x, W, b);

    // round 1: z = 0.85*(A_hat h) + 0.15*h
    k_scatter<<<(E_EDGES + 7) / 8, 256>>>(ei, /*src=h*/0);
    k_update <<<(TOT / 4 + 255) / 256, 256>>>(/*src=h*/0, out, /*use_out=*/0, /*clear=*/1);

    // round 2: out = 0.85*(A_hat z) + 0.15*h
    k_scatter<<<(E_EDGES + 7) / 8, 256>>>(ei, /*src=z*/1);
    k_update <<<(TOT / 4 + 255) / 256, 256>>>(/*src=z*/1, out, /*use_out=*/1, /*clear=*/0);
}

// round 4
// speedup vs baseline: 1.5770x; 1.5770x over previous
#include <cuda_runtime.h>
#include <cuda_bf16.h>
#include <cstdint>

#define N_NODES 50000
#define E_EDGES 600000
#define IN_DIM  256
#define OUT_DIM 128
#define SCALE   1.8f
#define ALPHA   0.15f
#define ONE_MA  0.85f

// ---------------------------------------------------------------- scratch
__device__ float g_h[(size_t)N_NODES * OUT_DIM];
__device__ float g_z[(size_t)N_NODES * OUT_DIM];
__device__ int   g_indeg[N_NODES];
__device__ int   g_off[N_NODES + 1];
__device__ int   g_cursor[N_NODES];
__device__ float g_dinv[N_NODES];
__device__ int   g_csr_src[E_EDGES];
__device__ float g_csr_w[E_EDGES];
__device__ __nv_bfloat16 g_xhi[(size_t)N_NODES * IN_DIM];
__device__ __nv_bfloat16 g_xlo[(size_t)N_NODES * IN_DIM];
__device__ __nv_bfloat16 g_whi[(size_t)OUT_DIM * IN_DIM];
__device__ __nv_bfloat16 g_wlo[(size_t)OUT_DIM * IN_DIM];

// ---------------------------------------------------------------- helpers
__device__ __forceinline__ uint32_t smem_u32(const void* p) {
    uint32_t a;
    asm("{ .reg .u64 t; cvta.to.shared.u64 t, %1; cvt.u32.u64 %0, t; }" : "=r"(a) : "l"(p));
    return a;
}
__device__ __forceinline__ void ldsm_x4(uint32_t* r, uint32_t addr) {
    asm volatile("ldmatrix.sync.aligned.m8n8.x4.shared.b16 {%0,%1,%2,%3}, [%4];"
                 : "=r"(r[0]), "=r"(r[1]), "=r"(r[2]), "=r"(r[3]) : "r"(addr));
}
__device__ __forceinline__ void mma_bf16(float* c, const uint32_t* a, const uint32_t* b) {
    asm volatile("mma.sync.aligned.m16n8k16.row.col.f32.bf16.bf16.f32 "
                 "{%0,%1,%2,%3}, {%4,%5,%6,%7}, {%8,%9}, {%0,%1,%2,%3};"
                 : "+f"(c[0]), "+f"(c[1]), "+f"(c[2]), "+f"(c[3])
                 : "r"(a[0]), "r"(a[1]), "r"(a[2]), "r"(a[3]), "r"(b[0]), "r"(b[1]));
}

// ---------------------------------------------------------------- bf16 split precompute
__global__ void k_split(const float* __restrict__ src, int which, int n) {
    int i = blockIdx.x * blockDim.x + threadIdx.x;     // pair index
    if (i * 2 >= n) return;
    float2 v = ((const float2*)src)[i];
    __nv_bfloat16 hx = __float2bfloat16(v.x), hy = __float2bfloat16(v.y);
    __nv_bfloat16 lx = __float2bfloat16(v.x - __bfloat162float(hx));
    __nv_bfloat16 ly = __float2bfloat16(v.y - __bfloat162float(hy));
    __nv_bfloat16* hi = which ? g_whi : g_xhi;
    __nv_bfloat16* lo = which ? g_wlo : g_xlo;
    ((__nv_bfloat162*)hi)[i] = __halves2bfloat162(hx, hy);
    ((__nv_bfloat162*)lo)[i] = __halves2bfloat162(lx, ly);
}

// ---------------------------------------------------------------- graph-norm build
__global__ void k_zero() {
    int i = blockIdx.x * blockDim.x + threadIdx.x;
    if (i < N_NODES) g_indeg[i] = 0;
}
__global__ void k_deg(const int* __restrict__ ei) {
    int e = blockIdx.x * blockDim.x + threadIdx.x;
    if (e < E_EDGES) atomicAdd(&g_indeg[ei[E_EDGES + e]], 1);
}
// single-block chunked exclusive scan of g_indeg -> g_off, g_cursor
__global__ void __launch_bounds__(1024) k_scan() {
    __shared__ int wsum[32];
    int lane = threadIdx.x & 31, wid = threadIdx.x >> 5;
    int carry = 0;
    for (int base = 0; base < N_NODES; base += 1024) {
        int i = base + threadIdx.x;
        int v = (i < N_NODES) ? g_indeg[i] : 0;
        int x = v;
#pragma unroll
        for (int d = 1; d < 32; d <<= 1) {
            int y = __shfl_up_sync(0xFFFFFFFFu, x, d);
            if (lane >= d) x += y;
        }
        if (lane == 31) wsum[wid] = x;
        __syncthreads();
        if (wid == 0) {
            int w = wsum[lane];
#pragma unroll
            for (int d = 1; d < 32; d <<= 1) {
                int y = __shfl_up_sync(0xFFFFFFFFu, w, d);
                if (lane >= d) w += y;
            }
            wsum[lane] = w;
        }
        __syncthreads();
        int excl = x - v + (wid > 0 ? wsum[wid - 1] : 0) + carry;
        if (i < N_NODES) { g_off[i] = excl; g_cursor[i] = excl; }
        carry += wsum[31];
        __syncthreads();
    }
    if (threadIdx.x == 0) g_off[N_NODES] = E_EDGES;
}
__global__ void k_dinv() {
    int i = blockIdx.x * blockDim.x + threadIdx.x;
    if (i < N_NODES) g_dinv[i] = rsqrtf((float)(g_indeg[i] + 1));
}
__global__ void k_place(const int* __restrict__ ei) {
    int e = blockIdx.x * blockDim.x + threadIdx.x;
    if (e < E_EDGES) {
        int r = ei[e];
        int c = ei[E_EDGES + e];
        int pos = atomicAdd(&g_cursor[c], 1);
        g_csr_src[pos] = r;
        g_csr_w[pos] = g_dinv[r] * g_dinv[c];
    }
}

// ---------------------------------------------------------------- HMMA GEMM
// h = normalize(x @ W^T + b) * SCALE  via bf16 2-split (hi*hi + hi*lo + lo*hi)
// CTA: 128 rows x 128 cols, 8 warps, warp = 32m x 64n, m16n8k16 fragments.
// smem tiles: [128 rows][32 k] bf16, row stride 40 elems (80 B, LDSM conflict-free).
#define RS 40
__global__ void __launch_bounds__(256) k_gemm_mma(const float* __restrict__ B) {
    __shared__ __nv_bfloat16 sAhi[128 * RS], sAlo[128 * RS];
    __shared__ __nv_bfloat16 sBhi[128 * RS], sBlo[128 * RS];
    __shared__ float s_bias[OUT_DIM];
    __shared__ float s_ssq[128][2];

    int tid = threadIdx.x, lane = tid & 31, wid = tid >> 5;
    int warp_m = wid & 3, warp_n = wid >> 2;
    int row0 = blockIdx.x * 128;
    if (tid < OUT_DIM) s_bias[tid] = B[tid];

    uint32_t aAhi = smem_u32(sAhi), aAlo = smem_u32(sAlo);
    uint32_t aBhi = smem_u32(sBhi), aBlo = smem_u32(sBlo);

    float c[2][8][4];
#pragma unroll
    for (int mi = 0; mi < 2; mi++)
#pragma unroll
        for (int nj = 0; nj < 8; nj++)
#pragma unroll
            for (int q = 0; q < 4; q++) c[mi][nj][q] = 0.f;

    uint32_t a_row = lane & 15;
    uint32_t a_kh  = lane >> 4;        // 0/1 -> k+8
    uint32_t b_g   = lane >> 3;        // ldmatrix matrix group 0..3
    uint32_t b_ln  = lane & 7;

    for (int step = 0; step < 8; step++) {
        int k0 = step * 32;
        // stage 128x32 bf16 x4 arrays (uint2 = 4 bf16 per ld/st)
        for (int t = tid; t < 1024; t += 256) {
            int r  = t >> 3;
            int cc = (t & 7) << 2;
            int so = r * RS + cc;
            int gr = row0 + r;
            uint2 v = make_uint2(0u, 0u);
            if (gr < N_NODES) v = *(const uint2*)(g_xhi + (size_t)gr * IN_DIM + k0 + cc);
            *(uint2*)(sAhi + so) = v;
            v = make_uint2(0u, 0u);
            if (gr < N_NODES) v = *(const uint2*)(g_xlo + (size_t)gr * IN_DIM + k0 + cc);
            *(uint2*)(sAlo + so) = v;
            *(uint2*)(sBhi + so) = *(const uint2*)(g_whi + (size_t)r * IN_DIM + k0 + cc);
            *(uint2*)(sBlo + so) = *(const uint2*)(g_wlo + (size_t)r * IN_DIM + k0 + cc);
        }
        __syncthreads();

#pragma unroll
        for (int kk = 0; kk < 32; kk += 16) {
            uint32_t ah[2][4], al[2][4];
#pragma unroll
            for (int mi = 0; mi < 2; mi++) {
                uint32_t off = (uint32_t)(warp_m * 32 + mi * 16 + a_row) * (RS * 2)
                             + (kk + a_kh * 8) * 2;
                ldsm_x4(ah[mi], aAhi + off);
                ldsm_x4(al[mi], aAlo + off);
            }
#pragma unroll
            for (int njp = 0; njp < 4; njp++) {
                uint32_t row = (uint32_t)(warp_n * 64 + njp * 16 + (b_g >> 1) * 8 + b_ln);
                uint32_t off = row * (RS * 2) + (kk + (b_g & 1) * 8) * 2;
                uint32_t bh[4], bl[4];
                ldsm_x4(bh, aBhi + off);
                ldsm_x4(bl, aBlo + off);
#pragma unroll
                for (int mi = 0; mi < 2; mi++) {
                    mma_bf16(c[mi][njp * 2],     ah[mi], bh);
                    mma_bf16(c[mi][njp * 2],     ah[mi], bl);
                    mma_bf16(c[mi][njp * 2],     al[mi], bh);
                    mma_bf16(c[mi][njp * 2 + 1], ah[mi], bh + 2);
                    mma_bf16(c[mi][njp * 2 + 1], ah[mi], bl + 2);
                    mma_bf16(c[mi][njp * 2 + 1], al[mi], bh + 2);
                }
            }
        }
        __syncthreads();
    }

    // epilogue: bias, row L2-norm across the two warp_n halves, scale, store
    int qr = lane >> 2;
    int qc = (lane & 3) * 2;
    float sq[2][2] = {{0.f, 0.f}, {0.f, 0.f}};
#pragma unroll
    for (int mi = 0; mi < 2; mi++)
#pragma unroll
        for (int nj = 0; nj < 8; nj++) {
            int colb = warp_n * 64 + nj * 8 + qc;
            float b0 = s_bias[colb], b1 = s_bias[colb + 1];
            c[mi][nj][0] += b0; c[mi][nj][1] += b1;
            c[mi][nj][2] += b0; c[mi][nj][3] += b1;
            sq[mi][0] += c[mi][nj][0] * c[mi][nj][0] + c[mi][nj][1] * c[mi][nj][1];
            sq[mi][1] += c[mi][nj][2] * c[mi][nj][2] + c[mi][nj][3] * c[mi][nj][3];
        }
#pragma unroll
    for (int mi = 0; mi < 2; mi++)
#pragma unroll
        for (int h = 0; h < 2; h++) {
            float v = sq[mi][h];
            v += __shfl_xor_sync(0xFFFFFFFFu, v, 1);
            v += __shfl_xor_sync(0xFFFFFFFFu, v, 2);
            if ((lane & 3) == 0)
                s_ssq[warp_m * 32 + mi * 16 + h * 8 + qr][warp_n] = v;
        }
    __syncthreads();
#pragma unroll
    for (int mi = 0; mi < 2; mi++)
#pragma unroll
        for (int h = 0; h < 2; h++) {
            int rloc = warp_m * 32 + mi * 16 + h * 8 + qr;
            float tot = s_ssq[rloc][0] + s_ssq[rloc][1];
            float s = SCALE / fmaxf(sqrtf(tot), 1e-12f);
            int gr = row0 + rloc;
            if (gr < N_NODES) {
                float* o = g_h + (size_t)gr * OUT_DIM + warp_n * 64 + qc;
#pragma unroll
                for (int nj = 0; nj < 8; nj++) {
                    float2 w2;
                    w2.x = c[mi][nj][h * 2] * s;
                    w2.y = c[mi][nj][h * 2 + 1] * s;
                    *(float2*)(o + nj * 8) = w2;
                }
            }
        }
}

// ---------------------------------------------------------------- CSR gather round
// dst[n] = 0.85*( sum_in w*src[s] + dinv[n]^2*src[n] ) + 0.15*h[n]
__global__ void __launch_bounds__(256) k_gather(int src_sel, float* __restrict__ out,
                                                int use_out) {
    int n = blockIdx.x * 8 + (threadIdx.x >> 5);
    int lane = threadIdx.x & 31;
    if (n >= N_NODES) return;

    const float* src = src_sel ? g_z : g_h;
    int e0 = g_off[n], e1 = g_off[n + 1];

    float4 acc = make_float4(0.f, 0.f, 0.f, 0.f);
    for (int e = e0; e < e1; e++) {
        int s = g_csr_src[e];
        float w = g_csr_w[e];
        float4 v = *(const float4*)(src + (size_t)s * OUT_DIM + lane * 4);
        acc.x += w * v.x; acc.y += w * v.y; acc.z += w * v.z; acc.w += w * v.w;
    }
    float dn = g_dinv[n];
    float sw = dn * dn;
    float4 cur = *(const float4*)(src + (size_t)n * OUT_DIM + lane * 4);
    float4 hh  = *(const float4*)(g_h + (size_t)n * OUT_DIM + lane * 4);
    float4 o;
    o.x = ONE_MA * (acc.x + sw * cur.x) + ALPHA * hh.x;
    o.y = ONE_MA * (acc.y + sw * cur.y) + ALPHA * hh.y;
    o.z = ONE_MA * (acc.z + sw * cur.z) + ALPHA * hh.z;
    o.w = ONE_MA * (acc.w + sw * cur.w) + ALPHA * hh.w;

    float* dst = use_out ? out : g_z;
    *(float4*)(dst + (size_t)n * OUT_DIM + lane * 4) = o;
}

// ----------------------------------------------------------------
extern "C" void kernel_launch(void* const* d_in, const int* in_sizes, int n_in,
                              void* d_out, int out_size) {
    const float* x  = (const float*)d_in[0];
    const int*   ei = (const int*)d_in[1];
    const float* W  = (const float*)d_in[2];
    const float* b  = (const float*)d_in[3];
    float* out = (float*)d_out;

    // graph-norm + CSR build
    k_zero <<<(N_NODES + 255) / 256, 256>>>();
    k_deg  <<<(E_EDGES + 255) / 256, 256>>>(ei);
    k_scan <<<1, 1024>>>();
    k_dinv <<<(N_NODES + 255) / 256, 256>>>();
    k_place<<<(E_EDGES + 255) / 256, 256>>>(ei);

    // bf16 splits
    k_split<<<(N_NODES * IN_DIM / 2 + 255) / 256, 256>>>(x, 0, N_NODES * IN_DIM);
    k_split<<<(OUT_DIM * IN_DIM / 2 + 255) / 256, 256>>>(W, 1, OUT_DIM * IN_DIM);

    // GEMM + fused bias/normalize
    k_gemm_mma<<<(N_NODES + 127) / 128, 256>>>(b);

    // APPNP rounds
    k_gather<<<(N_NODES + 7) / 8, 256>>>(0, out, 0);   // z   = prop(h)
    k_gather<<<(N_NODES + 7) / 8, 256>>>(1, out, 1);   // out = prop(z)
}

// round 5
// speedup vs baseline: 1.7545x; 1.1126x over previous
#include <cuda_runtime.h>
#include <cuda_bf16.h>
#include <cstdint>

#define N_NODES 50000
#define E_EDGES 600000
#define IN_DIM  256
#define OUT_DIM 128
#define SCALE   1.8f
#define ALPHA   0.15f
#define ONE_MA  0.85f

// ---------------------------------------------------------------- scratch
__device__ float g_h[(size_t)N_NODES * OUT_DIM];
__device__ float g_z[(size_t)N_NODES * OUT_DIM];
__device__ int   g_indeg[N_NODES];
__device__ int   g_off[N_NODES + 1];
__device__ int   g_cursor[N_NODES];
__device__ float g_dinv[N_NODES];
__device__ uint2 g_edge[E_EDGES];          // packed (src, weight)

// ---------------------------------------------------------------- helpers
__device__ __forceinline__ uint32_t smem_u32(const void* p) {
    uint32_t a;
    asm("{ .reg .u64 t; cvta.to.shared.u64 t, %1; cvt.u32.u64 %0, t; }" : "=r"(a) : "l"(p));
    return a;
}
__device__ __forceinline__ void ldsm_x4(uint32_t* r, uint32_t addr) {
    asm volatile("ldmatrix.sync.aligned.m8n8.x4.shared.b16 {%0,%1,%2,%3}, [%4];"
                 : "=r"(r[0]), "=r"(r[1]), "=r"(r[2]), "=r"(r[3]) : "r"(addr));
}
__device__ __forceinline__ void mma_bf16(float* c, const uint32_t* a, const uint32_t* b) {
    asm volatile("mma.sync.aligned.m16n8k16.row.col.f32.bf16.bf16.f32 "
                 "{%0,%1,%2,%3}, {%4,%5,%6,%7}, {%8,%9}, {%0,%1,%2,%3};"
                 : "+f"(c[0]), "+f"(c[1]), "+f"(c[2]), "+f"(c[3])
                 : "r"(a[0]), "r"(a[1]), "r"(a[2]), "r"(a[3]), "r"(b[0]), "r"(b[1]));
}
__device__ __forceinline__ void split2(float x, float y,
                                       __nv_bfloat162& hi, __nv_bfloat162& lo) {
    __nv_bfloat16 hx = __float2bfloat16(x), hy = __float2bfloat16(y);
    __nv_bfloat16 lx = __float2bfloat16(x - __bfloat162float(hx));
    __nv_bfloat16 ly = __float2bfloat16(y - __bfloat162float(hy));
    hi = __halves2bfloat162(hx, hy);
    lo = __halves2bfloat162(lx, ly);
}

// ---------------------------------------------------------------- graph-norm build
__global__ void k_zero() {
    int i = blockIdx.x * blockDim.x + threadIdx.x;
    if (i < N_NODES) g_indeg[i] = 0;
}
__global__ void k_deg(const int* __restrict__ ei) {
    int e = blockIdx.x * blockDim.x + threadIdx.x;
    if (e < E_EDGES) atomicAdd(&g_indeg[ei[E_EDGES + e]], 1);
}
// single-block chunked exclusive scan of g_indeg -> g_off/g_cursor, fused dinv
__global__ void __launch_bounds__(1024) k_scan() {
    __shared__ int wsum[32];
    int lane = threadIdx.x & 31, wid = threadIdx.x >> 5;
    int carry = 0;
    for (int base = 0; base < N_NODES; base += 1024) {
        int i = base + threadIdx.x;
        int v = (i < N_NODES) ? g_indeg[i] : 0;
        if (i < N_NODES) g_dinv[i] = rsqrtf((float)(v + 1));
        int x = v;
#pragma unroll
        for (int d = 1; d < 32; d <<= 1) {
            int y = __shfl_up_sync(0xFFFFFFFFu, x, d);
            if (lane >= d) x += y;
        }
        if (lane == 31) wsum[wid] = x;
        __syncthreads();
        if (wid == 0) {
            int w = wsum[lane];
#pragma unroll
            for (int d = 1; d < 32; d <<= 1) {
                int y = __shfl_up_sync(0xFFFFFFFFu, w, d);
                if (lane >= d) w += y;
            }
            wsum[lane] = w;
        }
        __syncthreads();
        int excl = x - v + (wid > 0 ? wsum[wid - 1] : 0) + carry;
        if (i < N_NODES) { g_off[i] = excl; g_cursor[i] = excl; }
        carry += wsum[31];
        __syncthreads();
    }
    if (threadIdx.x == 0) g_off[N_NODES] = E_EDGES;
}
__global__ void k_place(const int* __restrict__ ei) {
    int e = blockIdx.x * blockDim.x + threadIdx.x;
    if (e < E_EDGES) {
        int r = ei[e];
        int c = ei[E_EDGES + e];
        int pos = atomicAdd(&g_cursor[c], 1);
        float w = g_dinv[r] * g_dinv[c];
        g_edge[pos] = make_uint2((uint32_t)r, __float_as_uint(w));
    }
}

// ---------------------------------------------------------------- HMMA GEMM
// h = normalize(x @ W^T + b) * SCALE via bf16 2-split (hi*hi + hi*lo + lo*hi),
// split fused into the smem staging (reads fp32 X/W directly).
// CTA: 128 rows x 128 cols, 8 warps (warp = 32m x 64n), m16n8k16 fragments.
// smem tiles: [128 rows][32 k] bf16, row stride 40 elems (80 B, LDSM conflict-free).
#define RS 40
__global__ void __launch_bounds__(256) k_gemm_mma(const float* __restrict__ X,
                                                  const float* __restrict__ W,
                                                  const float* __restrict__ B) {
    __shared__ __nv_bfloat16 sAhi[128 * RS], sAlo[128 * RS];
    __shared__ __nv_bfloat16 sBhi[128 * RS], sBlo[128 * RS];
    __shared__ float s_bias[OUT_DIM];
    __shared__ float s_ssq[128][2];

    int tid = threadIdx.x, lane = tid & 31, wid = tid >> 5;
    int warp_m = wid & 3, warp_n = wid >> 2;
    int row0 = blockIdx.x * 128;
    if (tid < OUT_DIM) s_bias[tid] = B[tid];

    uint32_t aAhi = smem_u32(sAhi), aAlo = smem_u32(sAlo);
    uint32_t aBhi = smem_u32(sBhi), aBlo = smem_u32(sBlo);

    float c[2][8][4];
#pragma unroll
    for (int mi = 0; mi < 2; mi++)
#pragma unroll
        for (int nj = 0; nj < 8; nj++)
#pragma unroll
            for (int q = 0; q < 4; q++) c[mi][nj][q] = 0.f;

    uint32_t a_row = lane & 15;
    uint32_t a_kh  = lane >> 4;
    uint32_t b_g   = lane >> 3;
    uint32_t b_ln  = lane & 7;

    for (int step = 0; step < 8; step++) {
        int k0 = step * 32;
        // stage 128x32: load fp32, split hi/lo bf16 in-register
        for (int t = tid; t < 1024; t += 256) {
            int r  = t >> 3;
            int cc = (t & 7) << 2;
            int so = r * RS + cc;
            int gr = row0 + r;

            float4 xv = make_float4(0.f, 0.f, 0.f, 0.f);
            if (gr < N_NODES)
                xv = *(const float4*)(X + (size_t)gr * IN_DIM + k0 + cc);
            __nv_bfloat162 h01, h23, l01, l23;
            split2(xv.x, xv.y, h01, l01);
            split2(xv.z, xv.w, h23, l23);
            *(__nv_bfloat162*)(sAhi + so)     = h01;
            *(__nv_bfloat162*)(sAhi + so + 2) = h23;
            *(__nv_bfloat162*)(sAlo + so)     = l01;
            *(__nv_bfloat162*)(sAlo + so + 2) = l23;

            float4 wv = *(const float4*)(W + (size_t)r * IN_DIM + k0 + cc);
            split2(wv.x, wv.y, h01, l01);
            split2(wv.z, wv.w, h23, l23);
            *(__nv_bfloat162*)(sBhi + so)     = h01;
            *(__nv_bfloat162*)(sBhi + so + 2) = h23;
            *(__nv_bfloat162*)(sBlo + so)     = l01;
            *(__nv_bfloat162*)(sBlo + so + 2) = l23;
        }
        __syncthreads();

#pragma unroll
        for (int kk = 0; kk < 32; kk += 16) {
            uint32_t ah[2][4], al[2][4];
#pragma unroll
            for (int mi = 0; mi < 2; mi++) {
                uint32_t off = (uint32_t)(warp_m * 32 + mi * 16 + a_row) * (RS * 2)
                             + (kk + a_kh * 8) * 2;
                ldsm_x4(ah[mi], aAhi + off);
                ldsm_x4(al[mi], aAlo + off);
            }
#pragma unroll
            for (int njp = 0; njp < 4; njp++) {
                uint32_t row = (uint32_t)(warp_n * 64 + njp * 16 + (b_g >> 1) * 8 + b_ln);
                uint32_t off = row * (RS * 2) + (kk + (b_g & 1) * 8) * 2;
                uint32_t bh[4], bl[4];
                ldsm_x4(bh, aBhi + off);
                ldsm_x4(bl, aBlo + off);
#pragma unroll
                for (int mi = 0; mi < 2; mi++) {
                    mma_bf16(c[mi][njp * 2],     ah[mi], bh);
                    mma_bf16(c[mi][njp * 2],     ah[mi], bl);
                    mma_bf16(c[mi][njp * 2],     al[mi], bh);
                    mma_bf16(c[mi][njp * 2 + 1], ah[mi], bh + 2);
                    mma_bf16(c[mi][njp * 2 + 1], ah[mi], bl + 2);
                    mma_bf16(c[mi][njp * 2 + 1], al[mi], bh + 2);
                }
            }
        }
        __syncthreads();
    }

    // epilogue: bias, row L2-norm across two warp_n halves, scale, store
    int qr = lane >> 2;
    int qc = (lane & 3) * 2;
    float sq[2][2] = {{0.f, 0.f}, {0.f, 0.f}};
#pragma unroll
    for (int mi = 0; mi < 2; mi++)
#pragma unroll
        for (int nj = 0; nj < 8; nj++) {
            int colb = warp_n * 64 + nj * 8 + qc;
            float b0 = s_bias[colb], b1 = s_bias[colb + 1];
            c[mi][nj][0] += b0; c[mi][nj][1] += b1;
            c[mi][nj][2] += b0; c[mi][nj][3] += b1;
            sq[mi][0] += c[mi][nj][0] * c[mi][nj][0] + c[mi][nj][1] * c[mi][nj][1];
            sq[mi][1] += c[mi][nj][2] * c[mi][nj][2] + c[mi][nj][3] * c[mi][nj][3];
        }
#pragma unroll
    for (int mi = 0; mi < 2; mi++)
#pragma unroll
        for (int h = 0; h < 2; h++) {
            float v = sq[mi][h];
            v += __shfl_xor_sync(0xFFFFFFFFu, v, 1);
            v += __shfl_xor_sync(0xFFFFFFFFu, v, 2);
            if ((lane & 3) == 0)
                s_ssq[warp_m * 32 + mi * 16 + h * 8 + qr][warp_n] = v;
        }
    __syncthreads();
#pragma unroll
    for (int mi = 0; mi < 2; mi++)
#pragma unroll
        for (int h = 0; h < 2; h++) {
            int rloc = warp_m * 32 + mi * 16 + h * 8 + qr;
            float tot = s_ssq[rloc][0] + s_ssq[rloc][1];
            float s = SCALE / fmaxf(sqrtf(tot), 1e-12f);
            int gr = row0 + rloc;
            if (gr < N_NODES) {
                float* o = g_h + (size_t)gr * OUT_DIM + warp_n * 64 + qc;
#pragma unroll
                for (int nj = 0; nj < 8; nj++) {
                    float2 w2;
                    w2.x = c[mi][nj][h * 2] * s;
                    w2.y = c[mi][nj][h * 2 + 1] * s;
                    *(float2*)(o + nj * 8) = w2;
                }
            }
        }
}

// ---------------------------------------------------------------- gather round 1
// z[n] = 0.85*acc + (0.85*dinv^2 + 0.15)*h[n]   (src == h, rows fused)
__global__ void __launch_bounds__(256) k_gather1() {
    int n = blockIdx.x * 8 + (threadIdx.x >> 5);
    int lane = threadIdx.x & 31;
    if (n >= N_NODES) return;

    int e0 = g_off[n], e1 = g_off[n + 1];
    float4 acc = make_float4(0.f, 0.f, 0.f, 0.f);
#pragma unroll 2
    for (int e = e0; e < e1; e++) {
        uint2 ed = g_edge[e];
        float w = __uint_as_float(ed.y);
        float4 v = *(const float4*)(g_h + (size_t)ed.x * OUT_DIM + lane * 4);
        acc.x += w * v.x; acc.y += w * v.y; acc.z += w * v.z; acc.w += w * v.w;
    }
    float dn = g_dinv[n];
    float sc = ONE_MA * dn * dn + ALPHA;
    float4 hh = *(const float4*)(g_h + (size_t)n * OUT_DIM + lane * 4);
    float4 o;
    o.x = ONE_MA * acc.x + sc * hh.x;
    o.y = ONE_MA * acc.y + sc * hh.y;
    o.z = ONE_MA * acc.z + sc * hh.z;
    o.w = ONE_MA * acc.w + sc * hh.w;
    *(float4*)(g_z + (size_t)n * OUT_DIM + lane * 4) = o;
}

// ---------------------------------------------------------------- gather round 2
// out[n] = 0.85*(acc_z + dinv^2*z[n]) + 0.15*h[n]
__global__ void __launch_bounds__(256) k_gather2(float* __restrict__ out) {
    int n = blockIdx.x * 8 + (threadIdx.x >> 5);
    int lane = threadIdx.x & 31;
    if (n >= N_NODES) return;

    int e0 = g_off[n], e1 = g_off[n + 1];
    float4 acc = make_float4(0.f, 0.f, 0.f, 0.f);
#pragma unroll 2
    for (int e = e0; e < e1; e++) {
        uint2 ed = g_edge[e];
        float w = __uint_as_float(ed.y);
        float4 v = *(const float4*)(g_z + (size_t)ed.x * OUT_DIM + lane * 4);
        acc.x += w * v.x; acc.y += w * v.y; acc.z += w * v.z; acc.w += w * v.w;
    }
    float dn = g_dinv[n];
    float sw = dn * dn;
    float4 cur = *(const float4*)(g_z + (size_t)n * OUT_DIM + lane * 4);
    float4 hh  = *(const float4*)(g_h + (size_t)n * OUT_DIM + lane * 4);
    float4 o;
    o.x = ONE_MA * (acc.x + sw * cur.x) + ALPHA * hh.x;
    o.y = ONE_MA * (acc.y + sw * cur.y) + ALPHA * hh.y;
    o.z = ONE_MA * (acc.z + sw * cur.z) + ALPHA * hh.z;
    o.w = ONE_MA * (acc.w + sw * cur.w) + ALPHA * hh.w;
    *(float4*)(out + (size_t)n * OUT_DIM + lane * 4) = o;
}

// ----------------------------------------------------------------
extern "C" void kernel_launch(void* const* d_in, const int* in_sizes, int n_in,
                              void* d_out, int out_size) {
    const float* x  = (const float*)d_in[0];
    const int*   ei = (const int*)d_in[1];
    const float* W  = (const float*)d_in[2];
    const float* b  = (const float*)d_in[3];
    float* out = (float*)d_out;

    k_zero <<<(N_NODES + 255) / 256, 256>>>();
    k_deg  <<<(E_EDGES + 255) / 256, 256>>>(ei);
    k_scan <<<1, 1024>>>();
    k_place<<<(E_EDGES + 255) / 256, 256>>>(ei);

    k_gemm_mma<<<(N_NODES + 127) / 128, 256>>>(x, W, b);

    k_gather1<<<(N_NODES + 7) / 8, 256>>>();
    k_gather2<<<(N_NODES + 7) / 8, 256>>>(out);
}

// round 6
// speedup vs baseline: 2.0430x; 1.1644x over previous
#include <cuda_runtime.h>
#include <cuda_bf16.h>
#include <cstdint>

#define N_NODES 50000
#define E_EDGES 600000
#define IN_DIM  256
#define OUT_DIM 128
#define SCALE   1.8f
#define ALPHA   0.15f
#define ONE_MA  0.85f

// ---------------------------------------------------------------- scratch
__device__ float g_h[(size_t)N_NODES * OUT_DIM];
__device__ float g_z[(size_t)N_NODES * OUT_DIM];
__device__ __align__(16) int g_indeg[N_NODES];
__device__ int   g_off[N_NODES + 1];
__device__ int   g_cursor[N_NODES];
__device__ float g_dinv[N_NODES];
__device__ uint2 g_edge[E_EDGES];          // packed (src, weight)

// ---------------------------------------------------------------- helpers
__device__ __forceinline__ uint32_t smem_u32(const void* p) {
    uint32_t a;
    asm("{ .reg .u64 t; cvta.to.shared.u64 t, %1; cvt.u32.u64 %0, t; }" : "=r"(a) : "l"(p));
    return a;
}
__device__ __forceinline__ void ldsm_x4(uint32_t* r, uint32_t addr) {
    asm volatile("ldmatrix.sync.aligned.m8n8.x4.shared.b16 {%0,%1,%2,%3}, [%4];"
                 : "=r"(r[0]), "=r"(r[1]), "=r"(r[2]), "=r"(r[3]) : "r"(addr));
}
__device__ __forceinline__ void mma_bf16(float* c, const uint32_t* a, const uint32_t* b) {
    asm volatile("mma.sync.aligned.m16n8k16.row.col.f32.bf16.bf16.f32 "
                 "{%0,%1,%2,%3}, {%4,%5,%6,%7}, {%8,%9}, {%0,%1,%2,%3};"
                 : "+f"(c[0]), "+f"(c[1]), "+f"(c[2]), "+f"(c[3])
                 : "r"(a[0]), "r"(a[1]), "r"(a[2]), "r"(a[3]), "r"(b[0]), "r"(b[1]));
}
__device__ __forceinline__ void split2(float x, float y,
                                       __nv_bfloat162& hi, __nv_bfloat162& lo) {
    __nv_bfloat16 hx = __float2bfloat16(x), hy = __float2bfloat16(y);
    __nv_bfloat16 lx = __float2bfloat16(x - __bfloat162float(hx));
    __nv_bfloat16 ly = __float2bfloat16(y - __bfloat162float(hy));
    hi = __halves2bfloat162(hx, hy);
    lo = __halves2bfloat162(lx, ly);
}

// ---------------------------------------------------------------- graph-norm build
__global__ void k_zero() {
    int i = blockIdx.x * blockDim.x + threadIdx.x;
    if (i * 4 < N_NODES) {
        int4 z = make_int4(0, 0, 0, 0);
        *(int4*)(g_indeg + i * 4) = z;     // N_NODES % 4 == 0
    }
}
__global__ void k_deg(const int* __restrict__ ei) {
    int e = blockIdx.x * blockDim.x + threadIdx.x;
    if (e < E_EDGES) atomicAdd(&g_indeg[ei[E_EDGES + e]], 1);
}
// single-block exclusive scan, 4 elems/thread (int4), fused dinv
__global__ void __launch_bounds__(1024) k_scan() {
    __shared__ int wsum[32];
    int lane = threadIdx.x & 31, wid = threadIdx.x >> 5;
    int carry = 0;
    for (int base = 0; base < N_NODES; base += 4096) {
        int i4 = base + threadIdx.x * 4;
        int4 v = make_int4(0, 0, 0, 0);
        if (i4 < N_NODES) v = *(const int4*)(g_indeg + i4);   // N%4==0: full or none
        int vs = v.x + v.y + v.z + v.w;
        int x = vs;
#pragma unroll
        for (int d = 1; d < 32; d <<= 1) {
            int y = __shfl_up_sync(0xFFFFFFFFu, x, d);
            if (lane >= d) x += y;
        }
        if (lane == 31) wsum[wid] = x;
        __syncthreads();
        if (wid == 0) {
            int w = wsum[lane];
#pragma unroll
            for (int d = 1; d < 32; d <<= 1) {
                int y = __shfl_up_sync(0xFFFFFFFFu, w, d);
                if (lane >= d) w += y;
            }
            wsum[lane] = w;
        }
        __syncthreads();
        int excl = x - vs + (wid > 0 ? wsum[wid - 1] : 0) + carry;
        if (i4 < N_NODES) {
            int e0 = excl;
            int e1 = e0 + v.x;
            int e2 = e1 + v.y;
            int e3 = e2 + v.z;
            g_off[i4] = e0;     g_cursor[i4] = e0;
            g_off[i4 + 1] = e1; g_cursor[i4 + 1] = e1;
            g_off[i4 + 2] = e2; g_cursor[i4 + 2] = e2;
            g_off[i4 + 3] = e3; g_cursor[i4 + 3] = e3;
            g_dinv[i4]     = rsqrtf((float)(v.x + 1));
            g_dinv[i4 + 1] = rsqrtf((float)(v.y + 1));
            g_dinv[i4 + 2] = rsqrtf((float)(v.z + 1));
            g_dinv[i4 + 3] = rsqrtf((float)(v.w + 1));
        }
        carry += wsum[31];
        __syncthreads();
    }
    if (threadIdx.x == 0) g_off[N_NODES] = E_EDGES;
}
__global__ void k_place(const int* __restrict__ ei) {
    int e = blockIdx.x * blockDim.x + threadIdx.x;
    if (e < E_EDGES) {
        int r = ei[e];
        int c = ei[E_EDGES + e];
        int pos = atomicAdd(&g_cursor[c], 1);
        float w = g_dinv[r] * g_dinv[c];
        g_edge[pos] = make_uint2((uint32_t)r, __float_as_uint(w));
    }
}

// ---------------------------------------------------------------- HMMA GEMM
// h = normalize(x @ W^T + b) * SCALE via bf16 2-split (hi*hi + hi*lo + lo*hi),
// split fused into smem staging. CTA 128x128, 8 warps (32m x 64n), m16n8k16.
#define RS 40
__global__ void __launch_bounds__(256) k_gemm_mma(const float* __restrict__ X,
                                                  const float* __restrict__ W,
                                                  const float* __restrict__ B) {
    __shared__ __nv_bfloat16 sAhi[128 * RS], sAlo[128 * RS];
    __shared__ __nv_bfloat16 sBhi[128 * RS], sBlo[128 * RS];
    __shared__ float s_bias[OUT_DIM];
    __shared__ float s_ssq[128][2];

    int tid = threadIdx.x, lane = tid & 31, wid = tid >> 5;
    int warp_m = wid & 3, warp_n = wid >> 2;
    int row0 = blockIdx.x * 128;
    if (tid < OUT_DIM) s_bias[tid] = B[tid];

    uint32_t aAhi = smem_u32(sAhi), aAlo = smem_u32(sAlo);
    uint32_t aBhi = smem_u32(sBhi), aBlo = smem_u32(sBlo);

    float c[2][8][4];
#pragma unroll
    for (int mi = 0; mi < 2; mi++)
#pragma unroll
        for (int nj = 0; nj < 8; nj++)
#pragma unroll
            for (int q = 0; q < 4; q++) c[mi][nj][q] = 0.f;

    uint32_t a_row = lane & 15;
    uint32_t a_kh  = lane >> 4;
    uint32_t b_g   = lane >> 3;
    uint32_t b_ln  = lane & 7;

    for (int step = 0; step < 8; step++) {
        int k0 = step * 32;
        for (int t = tid; t < 1024; t += 256) {
            int r  = t >> 3;
            int cc = (t & 7) << 2;
            int so = r * RS + cc;
            int gr = row0 + r;

            float4 xv = make_float4(0.f, 0.f, 0.f, 0.f);
            if (gr < N_NODES)
                xv = *(const float4*)(X + (size_t)gr * IN_DIM + k0 + cc);
            __nv_bfloat162 h01, h23, l01, l23;
            split2(xv.x, xv.y, h01, l01);
            split2(xv.z, xv.w, h23, l23);
            *(__nv_bfloat162*)(sAhi + so)     = h01;
            *(__nv_bfloat162*)(sAhi + so + 2) = h23;
            *(__nv_bfloat162*)(sAlo + so)     = l01;
            *(__nv_bfloat162*)(sAlo + so + 2) = l23;

            float4 wv = *(const float4*)(W + (size_t)r * IN_DIM + k0 + cc);
            split2(wv.x, wv.y, h01, l01);
            split2(wv.z, wv.w, h23, l23);
            *(__nv_bfloat162*)(sBhi + so)     = h01;
            *(__nv_bfloat162*)(sBhi + so + 2) = h23;
            *(__nv_bfloat162*)(sBlo + so)     = l01;
            *(__nv_bfloat162*)(sBlo + so + 2) = l23;
        }
        __syncthreads();

#pragma unroll
        for (int kk = 0; kk < 32; kk += 16) {
            uint32_t ah[2][4], al[2][4];
#pragma unroll
            for (int mi = 0; mi < 2; mi++) {
                uint32_t off = (uint32_t)(warp_m * 32 + mi * 16 + a_row) * (RS * 2)
                             + (kk + a_kh * 8) * 2;
                ldsm_x4(ah[mi], aAhi + off);
                ldsm_x4(al[mi], aAlo + off);
            }
#pragma unroll
            for (int njp = 0; njp < 4; njp++) {
                uint32_t row = (uint32_t)(warp_n * 64 + njp * 16 + (b_g >> 1) * 8 + b_ln);
                uint32_t off = row * (RS * 2) + (kk + (b_g & 1) * 8) * 2;
                uint32_t bh[4], bl[4];
                ldsm_x4(bh, aBhi + off);
                ldsm_x4(bl, aBlo + off);
#pragma unroll
                for (int mi = 0; mi < 2; mi++) {
                    mma_bf16(c[mi][njp * 2],     ah[mi], bh);
                    mma_bf16(c[mi][njp * 2],     ah[mi], bl);
                    mma_bf16(c[mi][njp * 2],     al[mi], bh);
                    mma_bf16(c[mi][njp * 2 + 1], ah[mi], bh + 2);
                    mma_bf16(c[mi][njp * 2 + 1], ah[mi], bl + 2);
                    mma_bf16(c[mi][njp * 2 + 1], al[mi], bh + 2);
                }
            }
        }
        __syncthreads();
    }

    int qr = lane >> 2;
    int qc = (lane & 3) * 2;
    float sq[2][2] = {{0.f, 0.f}, {0.f, 0.f}};
#pragma unroll
    for (int mi = 0; mi < 2; mi++)
#pragma unroll
        for (int nj = 0; nj < 8; nj++) {
            int colb = warp_n * 64 + nj * 8 + qc;
            float b0 = s_bias[colb], b1 = s_bias[colb + 1];
            c[mi][nj][0] += b0; c[mi][nj][1] += b1;
            c[mi][nj][2] += b0; c[mi][nj][3] += b1;
            sq[mi][0] += c[mi][nj][0] * c[mi][nj][0] + c[mi][nj][1] * c[mi][nj][1];
            sq[mi][1] += c[mi][nj][2] * c[mi][nj][2] + c[mi][nj][3] * c[mi][nj][3];
        }
#pragma unroll
    for (int mi = 0; mi < 2; mi++)
#pragma unroll
        for (int h = 0; h < 2; h++) {
            float v = sq[mi][h];
            v += __shfl_xor_sync(0xFFFFFFFFu, v, 1);
            v += __shfl_xor_sync(0xFFFFFFFFu, v, 2);
            if ((lane & 3) == 0)
                s_ssq[warp_m * 32 + mi * 16 + h * 8 + qr][warp_n] = v;
        }
    __syncthreads();
#pragma unroll
    for (int mi = 0; mi < 2; mi++)
#pragma unroll
        for (int h = 0; h < 2; h++) {
            int rloc = warp_m * 32 + mi * 16 + h * 8 + qr;
            float tot = s_ssq[rloc][0] + s_ssq[rloc][1];
            float s = SCALE / fmaxf(sqrtf(tot), 1e-12f);
            int gr = row0 + rloc;
            if (gr < N_NODES) {
                float* o = g_h + (size_t)gr * OUT_DIM + warp_n * 64 + qc;
#pragma unroll
                for (int nj = 0; nj < 8; nj++) {
                    float2 w2;
                    w2.x = c[mi][nj][h * 2] * s;
                    w2.y = c[mi][nj][h * 2 + 1] * s;
                    *(float2*)(o + nj * 8) = w2;
                }
            }
        }
}

// ---------------------------------------------------------------- gather rounds
__global__ void __launch_bounds__(256) k_gather1() {
    int n = blockIdx.x * 8 + (threadIdx.x >> 5);
    int lane = threadIdx.x & 31;
    if (n >= N_NODES) return;

    int e0 = g_off[n], e1 = g_off[n + 1];
    float4 acc = make_float4(0.f, 0.f, 0.f, 0.f);
#pragma unroll 2
    for (int e = e0; e < e1; e++) {
        uint2 ed = g_edge[e];
        float w = __uint_as_float(ed.y);
        float4 v = __ldg((const float4*)(g_h + (size_t)ed.x * OUT_DIM + lane * 4));
        acc.x += w * v.x; acc.y += w * v.y; acc.z += w * v.z; acc.w += w * v.w;
    }
    float dn = g_dinv[n];
    float sc = ONE_MA * dn * dn + ALPHA;
    float4 hh = __ldg((const float4*)(g_h + (size_t)n * OUT_DIM + lane * 4));
    float4 o;
    o.x = ONE_MA * acc.x + sc * hh.x;
    o.y = ONE_MA * acc.y + sc * hh.y;
    o.z = ONE_MA * acc.z + sc * hh.z;
    o.w = ONE_MA * acc.w + sc * hh.w;
    *(float4*)(g_z + (size_t)n * OUT_DIM + lane * 4) = o;
}

__global__ void __launch_bounds__(256) k_gather2(float* __restrict__ out) {
    int n = blockIdx.x * 8 + (threadIdx.x >> 5);
    int lane = threadIdx.x & 31;
    if (n >= N_NODES) return;

    int e0 = g_off[n], e1 = g_off[n + 1];
    float4 acc = make_float4(0.f, 0.f, 0.f, 0.f);
#pragma unroll 2
    for (int e = e0; e < e1; e++) {
        uint2 ed = g_edge[e];
        float w = __uint_as_float(ed.y);
        float4 v = __ldg((const float4*)(g_z + (size_t)ed.x * OUT_DIM + lane * 4));
        acc.x += w * v.x; acc.y += w * v.y; acc.z += w * v.z; acc.w += w * v.w;
    }
    float dn = g_dinv[n];
    float sw = dn * dn;
    float4 cur = __ldg((const float4*)(g_z + (size_t)n * OUT_DIM + lane * 4));
    float4 hh  = __ldg((const float4*)(g_h + (size_t)n * OUT_DIM + lane * 4));
    float4 o;
    o.x = ONE_MA * (acc.x + sw * cur.x) + ALPHA * hh.x;
    o.y = ONE_MA * (acc.y + sw * cur.y) + ALPHA * hh.y;
    o.z = ONE_MA * (acc.z + sw * cur.z) + ALPHA * hh.z;
    o.w = ONE_MA * (acc.w + sw * cur.w) + ALPHA * hh.w;
    *(float4*)(out + (size_t)n * OUT_DIM + lane * 4) = o;
}

// ----------------------------------------------------------------
extern "C" void kernel_launch(void* const* d_in, const int* in_sizes, int n_in,
                              void* d_out, int out_size) {
    const float* x  = (const float*)d_in[0];
    const int*   ei = (const int*)d_in[1];
    const float* W  = (const float*)d_in[2];
    const float* b  = (const float*)d_in[3];
    float* out = (float*)d_out;

    // one-time side-stream + events (host resources only; no device memory)
    static cudaStream_t s2 = nullptr;
    static cudaEvent_t ev_fork = nullptr, ev_join = nullptr;
    if (s2 == nullptr) {
        cudaStreamCreateWithFlags(&s2, cudaStreamNonBlocking);
        cudaEventCreateWithFlags(&ev_fork, cudaEventDisableTiming);
        cudaEventCreateWithFlags(&ev_join, cudaEventDisableTiming);
    }

    // fork: CSR build on s2, GEMM on the main (capture) stream
    cudaEventRecord(ev_fork, 0);
    cudaStreamWaitEvent(s2, ev_fork, 0);

    k_zero <<<(N_NODES / 4 + 255) / 256, 256, 0, s2>>>();
    k_deg  <<<(E_EDGES + 255) / 256, 256, 0, s2>>>(ei);
    k_scan <<<1, 1024, 0, s2>>>();
    k_place<<<(E_EDGES + 255) / 256, 256, 0, s2>>>(ei);
    cudaEventRecord(ev_join, s2);

    k_gemm_mma<<<(N_NODES + 127) / 128, 256>>>(x, W, b);

    // join: gathers need both the GEMM (g_h) and the CSR build
    cudaStreamWaitEvent(0, ev_join, 0);
    k_gather1<<<(N_NODES + 7) / 8, 256>>>();
    k_gather2<<<(N_NODES + 7) / 8, 256>>>(out);
}